// round 2
// baseline (speedup 1.0000x reference)
#include <cuda_runtime.h>
#include <cooperative_groups.h>
#include <cstdint>

namespace cg = cooperative_groups;

// Problem constants
constexpr int B = 32;
constexpr int N = 131072;
constexpr int K = 1024;

// Config
constexpr int C  = 4;            // CTAs per batch (cluster)
constexpr int T  = 512;          // threads per CTA
constexpr int S  = N / C;        // 32768 points per CTA slice
constexpr int P  = S / T;        // 64 points per thread (dist in regs)
constexpr int SP = 18432;        // points pinned in SMEM
constexpr int SJ = SP / T;       // 36 pinned pts / thread
constexpr int GJ = (S - SP) / T; // 28 streamed pts / thread

// SoA scratch (static device arrays: allocation-free)
__device__ float g_sx[B * N];
__device__ float g_sy[B * N];
__device__ float g_sz[B * N];

__global__ void transpose_kernel(const float* __restrict__ pts) {
    int i = blockIdx.x * blockDim.x + threadIdx.x;
    if (i < B * N) {
        g_sx[i] = pts[3 * i + 0];
        g_sy[i] = pts[3 * i + 1];
        g_sz[i] = pts[3 * i + 2];
    }
}

// SMEM layout (bytes)
constexpr int SMEM_X  = 0;
constexpr int SMEM_Y  = SMEM_X + SP * 4;
constexpr int SMEM_Z  = SMEM_Y + SP * 4;
constexpr int SMEM_SL = SMEM_Z + SP * 4;   // slots[2][C] u64 (parity-double-buffered)
constexpr int SMEM_WB = SMEM_SL + 2 * C * 8; // wb[16] u64 warp-reduce scratch
constexpr int SMEM_TOTAL = SMEM_WB + 16 * 8; // 221,376 B

__global__ void __cluster_dims__(C, 1, 1) __launch_bounds__(T, 1)
fps_kernel(const int* __restrict__ init_idx, float* __restrict__ out)
{
    extern __shared__ char smem[];
    float* sx = (float*)(smem + SMEM_X);
    float* sy = (float*)(smem + SMEM_Y);
    float* sz = (float*)(smem + SMEM_Z);
    unsigned long long* sl = (unsigned long long*)(smem + SMEM_SL);
    unsigned long long* wb = (unsigned long long*)(smem + SMEM_WB);

    cg::cluster_group cluster = cg::this_cluster();
    const int rank  = blockIdx.x;        // 0..C-1
    const int b     = blockIdx.y;        // batch
    const int t     = threadIdx.x;
    const int lbase = rank * S;          // slice start within batch
    const int bOff  = b * N;             // batch start in SoA arrays
    const int gbase = bOff + lbase;
    const int warp  = t >> 5, lane = t & 31;

    // streamed-region base pointers for this thread
    const float* gx = g_sx + gbase + SP + t;
    const float* gy = g_sy + gbase + SP + t;
    const float* gz = g_sz + gbase + SP + t;

    // ---- init: pin coords to SMEM ----
    #pragma unroll
    for (int j = 0; j < SJ; j++) {
        int i = t + j * T;
        sx[i] = g_sx[gbase + i];
        sy[i] = g_sy[gbase + i];
        sz[i] = g_sz[gbase + i];
    }

    // dist lives entirely in registers
    float dist[P];
    #pragma unroll
    for (int j = 0; j < P; j++) dist[j] = 1e10f;

    // first selected point: broadcast read (all threads, same address)
    const int idx0 = init_idx[b];
    float lx = g_sx[bOff + idx0];
    float ly = g_sy[bOff + idx0];
    float lz = g_sz[bOff + idx0];
    if (rank == 0 && t == 0) {
        out[(b * K + 0) * 3 + 0] = lx;
        out[(b * K + 0) * 3 + 1] = ly;
        out[(b * K + 0) * 3 + 2] = lz;
    }
    __syncthreads();

    // ---- K-1 sequential FPS iterations ----
    for (int k = 1; k < K; k++) {
        float bd0 = -1.0f, bd1 = -1.0f;
        int   bi0 = 0,     bi1 = 0;

        // L2-streamed points first (front-batch the LDGs)
        #pragma unroll
        for (int j = 0; j < GJ; j++) {
            float dx = gx[j * T] - lx;
            float dy = gy[j * T] - ly;
            float dz = gz[j * T] - lz;
            float d2 = __fmaf_rn(dx, dx, __fmaf_rn(dy, dy, dz * dz));
            float dm = fminf(dist[SJ + j], d2);
            dist[SJ + j] = dm;
            if (dm > bd1) { bd1 = dm; bi1 = SP + t + j * T; }
        }
        // SMEM-pinned points
        #pragma unroll
        for (int j = 0; j < SJ; j++) {
            int l = t + j * T;
            float dx = sx[l] - lx;
            float dy = sy[l] - ly;
            float dz = sz[l] - lz;
            float d2 = __fmaf_rn(dx, dx, __fmaf_rn(dy, dy, dz * dz));
            float dm = fminf(dist[j], d2);
            dist[j] = dm;
            if (dm > bd0) { bd0 = dm; bi0 = l; }
        }
        // merge accumulators (bi1 indices always > bi0 indices, so strict >)
        if (bd1 > bd0) { bd0 = bd1; bi0 = bi1; }

        // pack (dist, ~idx): larger packed value == farther, ties -> lower idx
        unsigned long long best =
            ((unsigned long long)__float_as_uint(bd0) << 32) |
            (unsigned)(~(unsigned)(lbase + bi0));

        // warp reduce (16 warps)
        #pragma unroll
        for (int o = 16; o > 0; o >>= 1) {
            unsigned long long v = __shfl_down_sync(0xffffffffu, best, o);
            if (v > best) best = v;
        }
        if (lane == 0) wb[warp] = best;
        __syncthreads();

        // block reduce + push to all ranks (fire-and-forget remote stores)
        if (warp == 0) {
            best = (lane < 16) ? wb[lane] : 0ULL;
            #pragma unroll
            for (int o = 8; o > 0; o >>= 1) {
                unsigned long long v = __shfl_down_sync(0xffffffffu, best, o);
                if (v > best) best = v;
            }
            if (lane == 0) {
                unsigned long long* my_slot = &sl[(k & 1) * C + rank];
                #pragma unroll
                for (int r = 0; r < C; r++) {
                    unsigned long long* p =
                        (unsigned long long*)cluster.map_shared_rank(my_slot, r);
                    *p = best;
                }
            }
        }

        cluster.sync();  // orders remote slot stores; acquire for local reads

        // every thread redundantly picks the cluster winner (local LDS only)
        unsigned long long g0 = sl[(k & 1) * C + 0];
        unsigned long long g1 = sl[(k & 1) * C + 1];
        unsigned long long g2 = sl[(k & 1) * C + 2];
        unsigned long long g3 = sl[(k & 1) * C + 3];
        unsigned long long gb = g0;
        if (g1 > gb) gb = g1;
        if (g2 > gb) gb = g2;
        if (g3 > gb) gb = g3;
        unsigned widx = ~(unsigned)(gb & 0xffffffffull);

        // broadcast LDG of next point (one sector, all threads)
        lx = g_sx[bOff + widx];
        ly = g_sy[bOff + widx];
        lz = g_sz[bOff + widx];

        if (rank == 0 && t == 0) {
            out[(b * K + k) * 3 + 0] = lx;
            out[(b * K + k) * 3 + 1] = ly;
            out[(b * K + k) * 3 + 2] = lz;
        }
        // no trailing __syncthreads needed: next wb write is preceded by the
        // in-loop __syncthreads, and slot parity protects cross-iter reuse
    }

    cluster.sync();  // keep SMEM alive until all peer traffic has finished
}

extern "C" void kernel_launch(void* const* d_in, const int* in_sizes, int n_in,
                              void* d_out, int out_size) {
    const float* pts  = (const float*)d_in[0];
    const int*   init = (const int*)d_in[1];
    float*       out  = (float*)d_out;

    cudaFuncSetAttribute(fps_kernel,
                         cudaFuncAttributeMaxDynamicSharedMemorySize, SMEM_TOTAL);

    int total = B * N;
    transpose_kernel<<<(total + 255) / 256, 256>>>(pts);

    dim3 grid(C, B, 1);
    fps_kernel<<<grid, T, SMEM_TOTAL>>>(init, out);
}

// round 3
// speedup vs baseline: 1.4398x; 1.4398x over previous
#include <cuda_runtime.h>
#include <cooperative_groups.h>
#include <cstdint>

namespace cg = cooperative_groups;

// Problem constants
constexpr int B = 32;
constexpr int N = 131072;
constexpr int K = 1024;

// Config
constexpr int C   = 4;            // CTAs per batch (cluster)
constexpr int T   = 1024;         // threads per CTA (32 warps)
constexpr int S   = N / C;        // 32768 points per CTA slice
constexpr int PIN = 16384;        // pts: coords pinned in SMEM, dist in regs
constexpr int RS  = 8192;         // pts: coords streamed (L2), dist in regs
constexpr int SD  = 8192;         // pts: coords streamed (L2), dist in SMEM
static_assert(PIN + RS + SD == S, "partition");
constexpr int JP = PIN / T;       // 16 pinned iters/thread
constexpr int JR = RS / T;        // 8 reg-dist streamed iters/thread
constexpr int JS = SD / T;        // 8 smem-dist streamed iters/thread

// SoA scratch (static device arrays: allocation-free)
__device__ float g_sx[B * N];
__device__ float g_sy[B * N];
__device__ float g_sz[B * N];

__global__ void transpose_kernel(const float* __restrict__ pts) {
    int i = blockIdx.x * blockDim.x + threadIdx.x;
    if (i < B * N) {
        g_sx[i] = pts[3 * i + 0];
        g_sy[i] = pts[3 * i + 1];
        g_sz[i] = pts[3 * i + 2];
    }
}

// SMEM layout (bytes)
constexpr int SMEM_X  = 0;                     // PIN floats
constexpr int SMEM_Y  = SMEM_X + PIN * 4;
constexpr int SMEM_Z  = SMEM_Y + PIN * 4;
constexpr int SMEM_D  = SMEM_Z + PIN * 4;      // SD floats (smem dist)
constexpr int SMEM_SL = SMEM_D + SD * 4;       // slots[2][C] u64 (parity)
constexpr int SMEM_WB = SMEM_SL + 2 * C * 8;   // wb[32] u64
constexpr int SMEM_TOTAL = SMEM_WB + 32 * 8;   // 229,696 B <= 232,448 opt-in

__global__ void __cluster_dims__(C, 1, 1) __launch_bounds__(T, 1)
fps_kernel(const int* __restrict__ init_idx, float* __restrict__ out)
{
    extern __shared__ char smem[];
    float* sx = (float*)(smem + SMEM_X);
    float* sy = (float*)(smem + SMEM_Y);
    float* sz = (float*)(smem + SMEM_Z);
    float* sd = (float*)(smem + SMEM_D);
    unsigned long long* sl = (unsigned long long*)(smem + SMEM_SL);
    unsigned long long* wb = (unsigned long long*)(smem + SMEM_WB);

    cg::cluster_group cluster = cg::this_cluster();
    const int rank  = blockIdx.x;        // 0..C-1
    const int b     = blockIdx.y;        // batch
    const int t     = threadIdx.x;
    const int lbase = rank * S;          // slice start within batch
    const int bOff  = b * N;
    const int gbase = bOff + lbase;
    const int warp  = t >> 5, lane = t & 31;

    // streamed-region base pointers for this thread
    const float* __restrict__ gx = g_sx + gbase + PIN + t;
    const float* __restrict__ gy = g_sy + gbase + PIN + t;
    const float* __restrict__ gz = g_sz + gbase + PIN + t;

    // ---- init: pin coords, init smem dist ----
    #pragma unroll
    for (int j = 0; j < JP; j++) {
        int i = t + j * T;
        sx[i] = g_sx[gbase + i];
        sy[i] = g_sy[gbase + i];
        sz[i] = g_sz[gbase + i];
    }
    #pragma unroll
    for (int j = 0; j < JS; j++) sd[t + j * T] = 1e10f;

    // register-resident dist: [0..JP) pinned pts, [JP..JP+JR) streamed pts
    float dist[JP + JR];
    #pragma unroll
    for (int j = 0; j < JP + JR; j++) dist[j] = 1e10f;

    // first selected point (broadcast read)
    const int idx0 = init_idx[b];
    float lx = g_sx[bOff + idx0];
    float ly = g_sy[bOff + idx0];
    float lz = g_sz[bOff + idx0];
    if (rank == 0 && t == 0) {
        out[(b * K + 0) * 3 + 0] = lx;
        out[(b * K + 0) * 3 + 1] = ly;
        out[(b * K + 0) * 3 + 2] = lz;
    }
    __syncthreads();

    // ---- K-1 sequential FPS iterations ----
    for (int k = 1; k < K; k++) {
        // two accumulator chains: P covers low indices [0,PIN),
        // Q covers high indices [PIN,S) in ascending order
        float bdP = -1.0f, bdQ = -1.0f;
        int   biP = 0,     biQ = 0;

        // (1) streamed coords, reg dist  — indices [PIN, PIN+RS)
        #pragma unroll
        for (int j = 0; j < JR; j++) {
            float dx = gx[j * T] - lx;
            float dy = gy[j * T] - ly;
            float dz = gz[j * T] - lz;
            float d2 = __fmaf_rn(dx, dx, __fmaf_rn(dy, dy, dz * dz));
            float dm = fminf(dist[JP + j], d2);
            dist[JP + j] = dm;
            if (dm > bdQ) { bdQ = dm; biQ = PIN + t + j * T; }
        }
        // (2) streamed coords, smem dist — indices [PIN+RS, S)
        #pragma unroll
        for (int j = 0; j < JS; j++) {
            int l = t + j * T;                 // index into sd
            float dx = gx[RS + j * T] - lx;
            float dy = gy[RS + j * T] - ly;
            float dz = gz[RS + j * T] - lz;
            float d2 = __fmaf_rn(dx, dx, __fmaf_rn(dy, dy, dz * dz));
            float dc = sd[l];
            if (d2 < dc) { sd[l] = d2; dc = d2; }  // conditional STS
            if (dc > bdQ) { bdQ = dc; biQ = PIN + RS + l; }
        }
        // (3) pinned coords, reg dist    — indices [0, PIN)
        #pragma unroll
        for (int j = 0; j < JP; j++) {
            int l = t + j * T;
            float dx = sx[l] - lx;
            float dy = sy[l] - ly;
            float dz = sz[l] - lz;
            float d2 = __fmaf_rn(dx, dx, __fmaf_rn(dy, dy, dz * dz));
            float dm = fminf(dist[j], d2);
            dist[j] = dm;
            if (dm > bdP) { bdP = dm; biP = l; }
        }
        // merge: strict > keeps the lower-index chain on ties
        if (bdQ > bdP) { bdP = bdQ; biP = biQ; }

        // pack (dist, ~idx): larger == farther; ties -> lower index
        unsigned long long best =
            ((unsigned long long)__float_as_uint(bdP) << 32) |
            (unsigned)(~(unsigned)(lbase + biP));

        // warp reduce
        #pragma unroll
        for (int o = 16; o > 0; o >>= 1) {
            unsigned long long v = __shfl_down_sync(0xffffffffu, best, o);
            if (v > best) best = v;
        }
        if (lane == 0) wb[warp] = best;
        __syncthreads();

        // block reduce (32 warps) + push result to all ranks
        if (warp == 0) {
            best = wb[lane];
            #pragma unroll
            for (int o = 16; o > 0; o >>= 1) {
                unsigned long long v = __shfl_down_sync(0xffffffffu, best, o);
                if (v > best) best = v;
            }
            if (lane == 0) {
                unsigned long long* my_slot = &sl[(k & 1) * C + rank];
                #pragma unroll
                for (int r = 0; r < C; r++) {
                    unsigned long long* p =
                        (unsigned long long*)cluster.map_shared_rank(my_slot, r);
                    *p = best;
                }
            }
        }

        cluster.sync();  // orders remote slot stores; acquire for local reads

        // every thread picks the cluster winner from local slots
        unsigned long long g0 = sl[(k & 1) * C + 0];
        unsigned long long g1 = sl[(k & 1) * C + 1];
        unsigned long long g2 = sl[(k & 1) * C + 2];
        unsigned long long g3 = sl[(k & 1) * C + 3];
        unsigned long long gb = g0;
        if (g1 > gb) gb = g1;
        if (g2 > gb) gb = g2;
        if (g3 > gb) gb = g3;
        unsigned widx = ~(unsigned)(gb & 0xffffffffull);

        // broadcast fetch of the next selected point
        lx = g_sx[bOff + widx];
        ly = g_sy[bOff + widx];
        lz = g_sz[bOff + widx];

        if (rank == 0 && t == 0) {
            out[(b * K + k) * 3 + 0] = lx;
            out[(b * K + k) * 3 + 1] = ly;
            out[(b * K + k) * 3 + 2] = lz;
        }
    }

    cluster.sync();  // keep SMEM alive until all peer traffic has retired
}

extern "C" void kernel_launch(void* const* d_in, const int* in_sizes, int n_in,
                              void* d_out, int out_size) {
    const float* pts  = (const float*)d_in[0];
    const int*   init = (const int*)d_in[1];
    float*       out  = (float*)d_out;

    cudaFuncSetAttribute(fps_kernel,
                         cudaFuncAttributeMaxDynamicSharedMemorySize, SMEM_TOTAL);

    int total = B * N;
    transpose_kernel<<<(total + 255) / 256, 256>>>(pts);

    dim3 grid(C, B, 1);
    fps_kernel<<<grid, T, SMEM_TOTAL>>>(init, out);
}

// round 4
// speedup vs baseline: 1.5314x; 1.0636x over previous
#include <cuda_runtime.h>
#include <cooperative_groups.h>
#include <cstdint>

namespace cg = cooperative_groups;

// Problem constants
constexpr int B = 32;
constexpr int N = 131072;
constexpr int K = 1024;

// Config
constexpr int C   = 4;            // CTAs per batch (cluster)
constexpr int T   = 1024;         // threads per CTA (32 warps)
constexpr int S   = N / C;        // 32768 points per CTA slice
constexpr int PIN = 16384;        // points with coords pinned in SMEM
constexpr int STR = S - PIN;      // 16384 points streamed from L2
constexpr int JP  = PIN / (4 * T); // 4 float4-groups per thread (pinned)
constexpr int JQ  = STR / (4 * T); // 4 float4-groups per thread (streamed)

// SoA scratch (static device arrays: allocation-free)
__device__ float g_sx[B * N];
__device__ float g_sy[B * N];
__device__ float g_sz[B * N];

__global__ void transpose_kernel(const float* __restrict__ pts) {
    int i = blockIdx.x * blockDim.x + threadIdx.x;
    if (i < B * N) {
        g_sx[i] = pts[3 * i + 0];
        g_sy[i] = pts[3 * i + 1];
        g_sz[i] = pts[3 * i + 2];
    }
}

// Exchange slot: packed best + winner coords, 32B aligned
struct __align__(32) Slot {
    unsigned int lo, hi;   // packed best: (dist_bits << 32) | ~idx
    float x, y, z;
    float pad0, pad1, pad2;
};

// SMEM layout (bytes)
constexpr int SMEM_X  = 0;                       // PIN floats (as float4)
constexpr int SMEM_Y  = SMEM_X + PIN * 4;
constexpr int SMEM_Z  = SMEM_Y + PIN * 4;
constexpr int SMEM_SL = SMEM_Z + PIN * 4;        // Slot[2][C]
constexpr int SMEM_WB = SMEM_SL + 2 * C * 32;    // u64 wb[32]
constexpr int SMEM_TOTAL = SMEM_WB + 32 * 8;     // ~197 KB

__global__ void __cluster_dims__(C, 1, 1) __launch_bounds__(T, 1)
fps_kernel(const int* __restrict__ init_idx, float* __restrict__ out)
{
    extern __shared__ char smem[];
    float4* sx4 = (float4*)(smem + SMEM_X);
    float4* sy4 = (float4*)(smem + SMEM_Y);
    float4* sz4 = (float4*)(smem + SMEM_Z);
    Slot*   sl  = (Slot*)(smem + SMEM_SL);
    unsigned long long* wb = (unsigned long long*)(smem + SMEM_WB);

    cg::cluster_group cluster = cg::this_cluster();
    const int rank  = blockIdx.x;
    const int b     = blockIdx.y;
    const int t     = threadIdx.x;
    const int lbase = rank * S;          // slice start within batch
    const int bOff  = b * N;
    const int gbase = bOff + lbase;
    const int warp  = t >> 5, lane = t & 31;

    // float4 views of this CTA's slice in the SoA arrays
    const float4* __restrict__ gx4 = (const float4*)(g_sx + gbase);
    const float4* __restrict__ gy4 = (const float4*)(g_sy + gbase);
    const float4* __restrict__ gz4 = (const float4*)(g_sz + gbase);
    const int strBase = PIN / 4;         // streamed region start (float4 units)

    // ---- init: pin first PIN points' coords into SMEM (vectorized) ----
    #pragma unroll
    for (int j = 0; j < JP; j++) {
        int fi = t + j * T;
        sx4[fi] = gx4[fi];
        sy4[fi] = gy4[fi];
        sz4[fi] = gz4[fi];
    }

    // all dist in registers: [0,16) pinned, [16,32) streamed
    float dist[32];
    #pragma unroll
    for (int j = 0; j < 32; j++) dist[j] = 1e10f;

    // first selected point (broadcast read)
    const int idx0 = init_idx[b];
    float lx = g_sx[bOff + idx0];
    float ly = g_sy[bOff + idx0];
    float lz = g_sz[bOff + idx0];
    if (rank == 0 && t == 0) {
        out[(b * K + 0) * 3 + 0] = lx;
        out[(b * K + 0) * 3 + 1] = ly;
        out[(b * K + 0) * 3 + 2] = lz;
    }
    __syncthreads();

    // ---- K-1 sequential FPS iterations ----
    for (int k = 1; k < K; k++) {
        float bdP = -1.0f, bdQ = -1.0f;
        int   liP = 0,     liQ = 0;      // local index: j*4 + c (5 bits)

        // streamed points (front-batch the LDG.128s)
        #pragma unroll
        for (int j = 0; j < JQ; j++) {
            int fi = strBase + t + j * T;
            float4 vx = gx4[fi];
            float4 vy = gy4[fi];
            float4 vz = gz4[fi];
            #pragma unroll
            for (int c = 0; c < 4; c++) {
                float dx = ((const float*)&vx)[c] - lx;
                float dy = ((const float*)&vy)[c] - ly;
                float dz = ((const float*)&vz)[c] - lz;
                float d2 = __fmaf_rn(dx, dx, __fmaf_rn(dy, dy, dz * dz));
                int   r  = 16 + j * 4 + c;
                float dm = fminf(dist[r], d2);
                dist[r] = dm;
                if (dm > bdQ) { bdQ = dm; liQ = j * 4 + c; }
            }
        }
        // pinned points (LDS.128)
        #pragma unroll
        for (int j = 0; j < JP; j++) {
            int fi = t + j * T;
            float4 vx = sx4[fi];
            float4 vy = sy4[fi];
            float4 vz = sz4[fi];
            #pragma unroll
            for (int c = 0; c < 4; c++) {
                float dx = ((const float*)&vx)[c] - lx;
                float dy = ((const float*)&vy)[c] - ly;
                float dz = ((const float*)&vz)[c] - lz;
                float d2 = __fmaf_rn(dx, dx, __fmaf_rn(dy, dy, dz * dz));
                int   r  = j * 4 + c;
                float dm = fminf(dist[r], d2);
                dist[r] = dm;
                if (dm > bdP) { bdP = dm; liP = j * 4 + c; }
            }
        }

        // reconstruct global (within-batch) indices once per iteration
        // point index = lbase + 4*t + (j<<12) + c, local li = j*4+c
        int gP = lbase + 4 * t + ((liP >> 2) << 12) + (liP & 3);
        int gQ = lbase + PIN + 4 * t + ((liQ >> 2) << 12) + (liQ & 3);
        // merge (P indices all < Q indices; strict > keeps lower idx on ties)
        if (bdQ > bdP) { bdP = bdQ; gP = gQ; }

        // pack (dist, ~idx): larger packed == farther; ties -> lower index
        unsigned long long best =
            ((unsigned long long)__float_as_uint(bdP) << 32) |
            (unsigned)(~(unsigned)gP);

        // warp reduce
        #pragma unroll
        for (int o = 16; o > 0; o >>= 1) {
            unsigned long long v = __shfl_down_sync(0xffffffffu, best, o);
            if (v > best) best = v;
        }
        if (lane == 0) wb[warp] = best;
        __syncthreads();

        // block reduce + fetch candidate coords + push to all ranks
        if (warp == 0) {
            best = wb[lane];
            #pragma unroll
            for (int o = 16; o > 0; o >>= 1) {
                unsigned long long v = __shfl_down_sync(0xffffffffu, best, o);
                if (v > best) best = v;
            }
            if (lane == 0) {
                unsigned cidx = ~(unsigned)(best & 0xffffffffull); // in-batch idx
                int loc = (int)cidx - lbase;                       // in-slice idx
                float cx, cy, cz;
                if (loc < PIN) {   // candidate coords from local SMEM
                    cx = ((const float*)sx4)[loc];
                    cy = ((const float*)sy4)[loc];
                    cz = ((const float*)sz4)[loc];
                } else {           // from L2
                    cx = g_sx[bOff + cidx];
                    cy = g_sy[bOff + cidx];
                    cz = g_sz[bOff + cidx];
                }
                Slot* my = &sl[(k & 1) * C + rank];
                uint4 w = make_uint4((unsigned)(best & 0xffffffffull),
                                     (unsigned)(best >> 32),
                                     __float_as_uint(cx),
                                     __float_as_uint(cy));
                #pragma unroll
                for (int r = 0; r < C; r++) {
                    Slot* p = (Slot*)cluster.map_shared_rank(my, r);
                    *(uint4*)p = w;
                    p->z = cz;
                }
            }
        }

        cluster.sync();  // orders remote slot stores; acquire for local reads

        // every thread picks the cluster winner from local slots (coords included)
        unsigned long long gb = 0ULL;
        float nx = 0.f, ny = 0.f, nz = 0.f;
        #pragma unroll
        for (int r = 0; r < C; r++) {
            const Slot* p = &sl[(k & 1) * C + r];
            uint4 w = *(const uint4*)p;
            float z = p->z;
            unsigned long long v = ((unsigned long long)w.y << 32) | w.x;
            if (v > gb) {
                gb = v;
                nx = __uint_as_float(w.z);
                ny = __uint_as_float(w.w);
                nz = z;
            }
        }
        lx = nx; ly = ny; lz = nz;

        if (rank == 0 && t == 0) {
            out[(b * K + k) * 3 + 0] = lx;
            out[(b * K + k) * 3 + 1] = ly;
            out[(b * K + k) * 3 + 2] = lz;
        }
    }

    cluster.sync();  // keep SMEM alive until all peer traffic has retired
}

extern "C" void kernel_launch(void* const* d_in, const int* in_sizes, int n_in,
                              void* d_out, int out_size) {
    const float* pts  = (const float*)d_in[0];
    const int*   init = (const int*)d_in[1];
    float*       out  = (float*)d_out;

    cudaFuncSetAttribute(fps_kernel,
                         cudaFuncAttributeMaxDynamicSharedMemorySize, SMEM_TOTAL);

    int total = B * N;
    transpose_kernel<<<(total + 255) / 256, 256>>>(pts);

    dim3 grid(C, B, 1);
    fps_kernel<<<grid, T, SMEM_TOTAL>>>(init, out);
}